// round 2
// baseline (speedup 1.0000x reference)
#include <cuda_runtime.h>
#include <cstdint>

// Problem constants
#define RB     128          // batch
#define RROUTE 4608         // routes (r)
#define CCO    160          // C*O = 10*16
#define II     8            // inner dim i

// K-split config
#define NSPLIT 144          // CTAs, one wave on 148 SMs
#define CHUNK  32           // routes per CTA  (144*32 = 4608)
#define RT     2            // routes per pipeline stage
#define NSTAGE (CHUNK / RT) // 16

// Partial results scratch: [NSPLIT][B][CO]
__device__ float g_partial[NSPLIT * RB * CCO];

__device__ __forceinline__ unsigned smem_u32(const void* p) {
    return (unsigned)__cvta_generic_to_shared(p);
}
__device__ __forceinline__ void cp16(unsigned dst, const void* src) {
    asm volatile("cp.async.cg.shared.global [%0], [%1], 16;" :: "r"(dst), "l"(src));
}
__device__ __forceinline__ void cp_commit() { asm volatile("cp.async.commit_group;"); }
__device__ __forceinline__ void cp_wait0()  { asm volatile("cp.async.wait_group 0;"); }

// Packed f32x2 FMA: d = a*b + d (element-wise on 2 packed fp32)
__device__ __forceinline__ void ffma2(unsigned long long& d,
                                      unsigned long long a,
                                      unsigned long long b) {
    asm("fma.rn.f32x2 %0, %1, %2, %0;" : "+l"(d) : "l"(a), "l"(b));
}
// Duplicate a scalar float into both halves of an f32x2
__device__ __forceinline__ unsigned long long dup2(float x) {
    unsigned long long d;
    unsigned u = __float_as_uint(x);
    asm("mov.b64 %0, {%1, %1};" : "=l"(d) : "r"(u));
    return d;
}

// ---------------------------------------------------------------------------
// Kernel 1: partial GEMM.  Each CTA handles CHUNK routes, computing the full
// [128 x 160] partial sum  partial[b,co] = sum_{r in chunk, i} x[b,r,i]*W[r,co,i]
// Thread tile: 8 b x 8 co (as 4 f32x2 pairs over co), 320 threads cover 16x20 tiles.
// Static smem: 24576 (xs) + 20480 (ws) = 45056 B < 48 KB.
// ---------------------------------------------------------------------------
__global__ void __launch_bounds__(320, 1)
digitcaps_partial_kernel(const float* __restrict__ x, const float* __restrict__ W)
{
    // xs: [stage][rr][b][12]  (8 valid floats + 4 pad to kill 256B-stride conflicts)
    __shared__ __align__(16) float xs[2][RT][RB][12];
    // ws: [stage][rr][i][co]  (transposed: co contiguous -> f32x2 pairs for free)
    __shared__ __align__(16) float ws[2][RT][II][CCO];

    const int tid = threadIdx.x;
    const int bt  = tid & 15;    // b tile   0..15
    const int ct  = tid >> 4;    // co tile  0..19
    const int b0  = bt * 8;
    const int co0 = ct * 8;
    const int r0  = blockIdx.x * CHUNK;

    // W-load assignment: thread handles (co = tid>>1, i4 = (tid&1)*4) per route
    const int wco = tid >> 1;
    const int wi4 = (tid & 1) * 4;
    // Base pointer for this thread's W element stream (route-major stride CCO*II)
    const float* wbase = W + ((size_t)r0 * CCO + wco) * II + wi4;

    unsigned long long acc[8][4];
#pragma unroll
    for (int bb = 0; bb < 8; bb++)
#pragma unroll
        for (int p = 0; p < 4; p++) acc[bb][p] = 0ull;

    float4 wr0, wr1;  // W prefetch registers (2 routes x 4 floats)

    // --- stage loaders ---
    auto issue_x = [&](int sb, int rbase) {
#pragma unroll
        for (int t = 0; t < 2; t++) {
            int q = tid + t * 320;
            if (q < 512) {                       // RT*128*2 = 512 16B chunks
                int rr   = q >> 8;
                int b    = (q >> 1) & 127;
                int half = q & 1;
                const float* src = x + ((size_t)b * RROUTE + (rbase + rr)) * II + half * 4;
                cp16(smem_u32(&xs[sb][rr][b][half * 4]), src);
            }
        }
        cp_commit();
    };
    auto issue_w = [&](int srel) {   // srel = stage index within chunk
        const float* p = wbase + (size_t)(srel * RT) * (CCO * II);
        wr0 = __ldg((const float4*)(p));
        wr1 = __ldg((const float4*)(p + (size_t)CCO * II));
    };
    auto store_w = [&](int sb) {
        ws[sb][0][wi4 + 0][wco] = wr0.x;
        ws[sb][0][wi4 + 1][wco] = wr0.y;
        ws[sb][0][wi4 + 2][wco] = wr0.z;
        ws[sb][0][wi4 + 3][wco] = wr0.w;
        ws[sb][1][wi4 + 0][wco] = wr1.x;
        ws[sb][1][wi4 + 1][wco] = wr1.y;
        ws[sb][1][wi4 + 2][wco] = wr1.z;
        ws[sb][1][wi4 + 3][wco] = wr1.w;
    };

    // --- prologue: fill stage 0 ---
    issue_x(0, r0);
    issue_w(0);
    store_w(0);
    cp_wait0();
    __syncthreads();

    int buf = 0;
#pragma unroll 1
    for (int s = 0; s < NSTAGE; s++) {
        const int nb = buf ^ 1;
        if (s + 1 < NSTAGE) {
            issue_x(nb, r0 + (s + 1) * RT);   // async, lands during compute
            issue_w(s + 1);                   // LDG issued early, consumed after compute
        }

        // ---- compute stage `buf` ----
#pragma unroll
        for (int rr = 0; rr < RT; rr++) {
            float4 xv[16];
#pragma unroll
            for (int bb = 0; bb < 8; bb++) {
                xv[2 * bb + 0] = *(const float4*)&xs[buf][rr][b0 + bb][0];
                xv[2 * bb + 1] = *(const float4*)&xs[buf][rr][b0 + bb][4];
            }
#pragma unroll
            for (int i = 0; i < 8; i++) {
                ulonglong2 wA = *(const ulonglong2*)&ws[buf][rr][i][co0];
                ulonglong2 wB = *(const ulonglong2*)&ws[buf][rr][i][co0 + 4];
#pragma unroll
                for (int bb = 0; bb < 8; bb++) {
                    const float4& v = xv[2 * bb + (i >> 2)];
                    float xf;
                    switch (i & 3) {
                        case 0:  xf = v.x; break;
                        case 1:  xf = v.y; break;
                        case 2:  xf = v.z; break;
                        default: xf = v.w; break;
                    }
                    unsigned long long xd = dup2(xf);
                    ffma2(acc[bb][0], xd, wA.x);
                    ffma2(acc[bb][1], xd, wA.y);
                    ffma2(acc[bb][2], xd, wB.x);
                    ffma2(acc[bb][3], xd, wB.y);
                }
            }
        }

        if (s + 1 < NSTAGE) {
            store_w(nb);
            cp_wait0();
        }
        __syncthreads();
        buf = nb;
    }

    // ---- write partial tile ----
    float* op = g_partial + (size_t)blockIdx.x * (RB * CCO);
#pragma unroll
    for (int bb = 0; bb < 8; bb++) {
#pragma unroll
        for (int p = 0; p < 4; p++) {
            unsigned long long u = acc[bb][p];
            float2 v;
            v.x = __uint_as_float((unsigned)(u & 0xffffffffull));
            v.y = __uint_as_float((unsigned)(u >> 32));
            *(float2*)&op[(b0 + bb) * CCO + co0 + 2 * p] = v;
        }
    }
}

// ---------------------------------------------------------------------------
// Kernel 2: reduce partials over NSPLIT, apply squash, write [B, C, O] output.
// grid = 128 (b), block = 160 (co).  Groups of 16 lanes share one capsule c.
// ---------------------------------------------------------------------------
__global__ void digitcaps_squash_kernel(float* __restrict__ out)
{
    const int b = blockIdx.x;
    const int t = threadIdx.x;           // co index 0..159
    const float* p = g_partial + (size_t)b * CCO + t;

    float ssum = 0.f;
#pragma unroll 8
    for (int k = 0; k < NSPLIT; k++)
        ssum += p[(size_t)k * (RB * CCO)];

    float s = ssum * (1.0f / (float)RROUTE);

    // sq_norm over the 16 'o' lanes of this capsule (16-lane segments align
    // with capsules since blockDim=160=5 full warps and t = c*16 + o)
    float sq = s * s;
#pragma unroll
    for (int m = 8; m >= 1; m >>= 1)
        sq += __shfl_xor_sync(0xffffffffu, sq, m, 16);

    float scale = sqrtf(sq) / (1.0f + sq);
    out[(size_t)b * CCO + t] = s * scale;
}

// ---------------------------------------------------------------------------
extern "C" void kernel_launch(void* const* d_in, const int* in_sizes, int n_in,
                              void* d_out, int out_size)
{
    const float* x = (const float*)d_in[0];   // [128, 4608, 8]
    const float* W = (const float*)d_in[1];   // [1, 4608, 10, 16, 8]
    float* out = (float*)d_out;               // [128, 10, 16]

    digitcaps_partial_kernel<<<NSPLIT, 320>>>(x, W);
    digitcaps_squash_kernel<<<RB, CCO>>>(out);
}

// round 6
// speedup vs baseline: 4.8336x; 4.8336x over previous
#include <cuda_runtime.h>
#include <cstdint>

// Problem constants
#define RB      128         // batch  (GEMM N)
#define RROUTE  4608        // routes
#define CCO     160         // C*O    (GEMM M)
#define II      8

// K-split
#define NSPLIT  144         // CTAs
#define CHUNK_R 32          // routes per CTA (K=256)
#define CK_R    4           // routes per k-chunk
#define KCH     32          // k per chunk
#define NCH     8
#define NTHREADS 512

// smem rows (bytes), padded & 16B aligned, ldmatrix conflict-free
#define A_ROW   80          // W tile row: 40 bf16 (32 used)
#define B_ROW   272         // x tile row: 136 bf16 (128 used)
#define OFF_AHI 0
#define OFF_ALO (CCO * A_ROW)            // 12800
#define OFF_BHI (2 * CCO * A_ROW)        // 25600
#define OFF_BLO (OFF_BHI + KCH * B_ROW)  // 34304
#define BUFB    (OFF_BLO + KCH * B_ROW)  // 43008  (single buffer, static smem < 48KB)

// partial results [NSPLIT][B][CO]
__device__ float g_partial[NSPLIT * RB * CCO];

// ---------------- helpers ----------------
__device__ __forceinline__ uint32_t smem_u32(const void* p) {
    uint32_t a;
    asm("{ .reg .u64 t; cvta.to.shared.u64 t, %1; cvt.u32.u64 %0, t; }" : "=r"(a) : "l"(p));
    return a;
}
// pack two f32 -> bf16x2 (e0 low half, e1 high half)
__device__ __forceinline__ uint32_t packbf(float e0, float e1) {
    uint32_t d;
    asm("cvt.rn.bf16x2.f32 %0, %1, %2;" : "=r"(d) : "f"(e1), "f"(e0));
    return d;
}
__device__ __forceinline__ float lo_f32(uint32_t h) { return __uint_as_float(h << 16); }
__device__ __forceinline__ float hi_f32(uint32_t h) { return __uint_as_float(h & 0xffff0000u); }

__device__ __forceinline__ void sts32(uint32_t a, uint32_t r) {
    asm volatile("st.shared.b32 [%0], %1;" :: "r"(a), "r"(r) : "memory");
}
__device__ __forceinline__ void sts64(uint32_t a, uint32_t r0, uint32_t r1) {
    asm volatile("st.shared.v2.b32 [%0], {%1, %2};" :: "r"(a), "r"(r0), "r"(r1) : "memory");
}
__device__ __forceinline__ void ldmx4(uint32_t* r, uint32_t a) {
    asm volatile("ldmatrix.sync.aligned.m8n8.x4.shared.b16 {%0,%1,%2,%3}, [%4];"
                 : "=r"(r[0]), "=r"(r[1]), "=r"(r[2]), "=r"(r[3]) : "r"(a));
}
__device__ __forceinline__ void ldmx2t(uint32_t* r, uint32_t a) {
    asm volatile("ldmatrix.sync.aligned.m8n8.x2.trans.shared.b16 {%0,%1}, [%2];"
                 : "=r"(r[0]), "=r"(r[1]) : "r"(a));
}
__device__ __forceinline__ void mma16816(float* d, const uint32_t* a, const uint32_t* b) {
    asm volatile(
        "mma.sync.aligned.m16n8k16.row.col.f32.bf16.bf16.f32 "
        "{%0,%1,%2,%3}, {%4,%5,%6,%7}, {%8,%9}, {%0,%1,%2,%3};"
        : "+f"(d[0]), "+f"(d[1]), "+f"(d[2]), "+f"(d[3])
        : "r"(a[0]), "r"(a[1]), "r"(a[2]), "r"(a[3]), "r"(b[0]), "r"(b[1]));
}
__device__ __forceinline__ float f4elem(const float4& v, int j) {
    switch (j) { case 0: return v.x; case 1: return v.y; case 2: return v.z; default: return v.w; }
}

// ---------------------------------------------------------------------------
// Kernel 1: split-precision bf16 mma.sync partial GEMM.
// D[co][b] (per CTA) = sum_{k in 256-slab} W_k[co] * x_k[b]
// 16 warps: 2 (M=co, 80 each) x 8 (N=b, 16 each). Warp tile 80x16 = 5x2 mma tiles.
// Single 43KB static smem buffer; LDG prefetch in registers overlaps compute.
// ---------------------------------------------------------------------------
__global__ void __launch_bounds__(NTHREADS, 1)
digitcaps_mma_kernel(const float* __restrict__ x, const float* __restrict__ W)
{
    __shared__ __align__(16) char smem_raw[BUFB];
    const uint32_t tiles = smem_u32(smem_raw);

    const int tid = threadIdx.x;
    const int lid = tid & 31;
    const int wid = tid >> 5;
    const int wm  = wid & 1;          // M-warp (co)
    const int wn  = wid >> 1;         // N-warp (b)
    const int c0w = wm * 80;
    const int b0w = wn * 16;
    const int r0  = blockIdx.x * CHUNK_R;

    // x conversion task: b-pair bp, quarter q (k = q*4 + j)
    const int bp = tid >> 3;
    const int q  = tid & 7;

    float acc[5][2][4];
#pragma unroll
    for (int mt = 0; mt < 5; mt++)
#pragma unroll
        for (int nt = 0; nt < 2; nt++)
#pragma unroll
            for (int e = 0; e < 4; e++) acc[mt][nt][e] = 0.f;

    float4 px0, px1, pw[3];

    auto ldg_chunk = [&](int ck) {
        const int rc0 = r0 + ck * CK_R;
        const float4* xb = (const float4*)(x + ((size_t)(2 * bp) * RROUTE + rc0) * II);
        px0 = __ldg(xb + q);
        px1 = __ldg(xb + (RROUTE * II / 4) + q);     // row b+1
#pragma unroll
        for (int t = 0; t < 3; t++) {
            int idx = tid + t * NTHREADS;
            if (idx < 1280) {
                int rr = idx / 320, rem = idx - rr * 320;
                int co = rem >> 1, ih = rem & 1;
                pw[t] = __ldg((const float4*)(W + ((size_t)(rc0 + rr) * CCO + co) * II) + ih);
            }
        }
    };

    auto sts_chunk = [&]() {
        // x -> B tile [k][b] (transpose during store; bf16 pair (b, b+1) per word)
#pragma unroll
        for (int j = 0; j < 4; j++) {
            float e0 = f4elem(px0, j), e1 = f4elem(px1, j);
            uint32_t h = packbf(e0, e1);
            uint32_t l = packbf(e0 - lo_f32(h), e1 - hi_f32(h));
            uint32_t off = (uint32_t)((q * 4 + j) * B_ROW + 4 * bp);
            sts32(tiles + OFF_BHI + off, h);
            sts32(tiles + OFF_BLO + off, l);
        }
        // W -> A tile [co][k] (natural, k-contiguous)
#pragma unroll
        for (int t = 0; t < 3; t++) {
            int idx = tid + t * NTHREADS;
            if (idx < 1280) {
                int rr = idx / 320, rem = idx - rr * 320;
                int co = rem >> 1, ih = rem & 1;
                uint32_t h0 = packbf(pw[t].x, pw[t].y), h1 = packbf(pw[t].z, pw[t].w);
                uint32_t l0 = packbf(pw[t].x - lo_f32(h0), pw[t].y - hi_f32(h0));
                uint32_t l1 = packbf(pw[t].z - lo_f32(h1), pw[t].w - hi_f32(h1));
                uint32_t off = (uint32_t)(co * A_ROW + rr * 16 + ih * 8);
                sts64(tiles + OFF_AHI + off, h0, h1);
                sts64(tiles + OFF_ALO + off, l0, l1);
            }
        }
    };

    auto compute = [&]() {
#pragma unroll
        for (int ks = 0; ks < 2; ks++) {
            const uint32_t k0 = ks * 16;
            // B frags (x): 2 n-tiles, trans-ldmatrix from [k][b]
            uint32_t bh[2][2], bl[2][2];
            const uint32_t brow = k0 + (lid & 7) + ((lid >> 3) & 1) * 8;
#pragma unroll
            for (int nt = 0; nt < 2; nt++) {
                uint32_t a = tiles + OFF_BHI + brow * B_ROW + (uint32_t)(b0w + nt * 8) * 2;
                ldmx2t(bh[nt], a);
                ldmx2t(bl[nt], a + (OFF_BLO - OFF_BHI));
            }
#pragma unroll
            for (int mt = 0; mt < 5; mt++) {
                uint32_t ah[4], al[4];
                uint32_t a = tiles + OFF_AHI
                           + (uint32_t)(c0w + mt * 16 + (lid & 15)) * A_ROW
                           + (k0 + (lid >> 4) * 8) * 2;
                ldmx4(ah, a);
                ldmx4(al, a + (OFF_ALO - OFF_AHI));
#pragma unroll
                for (int nt = 0; nt < 2; nt++) {
                    mma16816(acc[mt][nt], ah, bh[nt]);
                    mma16816(acc[mt][nt], ah, bl[nt]);
                    mma16816(acc[mt][nt], al, bh[nt]);
                }
            }
        }
    };

    // pipeline: LDG(c) held in registers during compute(c-1); STS serialized
    ldg_chunk(0);
#pragma unroll 1
    for (int c = 0; c < NCH; c++) {
        sts_chunk();
        __syncthreads();
        if (c + 1 < NCH) ldg_chunk(c + 1);   // long-latency LDG overlaps compute
        compute();
        __syncthreads();                      // buffer reuse barrier
    }

    // epilogue: acc -> g_partial[bid][b][co]
    float* op = g_partial + (size_t)blockIdx.x * (RB * CCO);
    const int rl = lid >> 2;
    const int cl = 2 * (lid & 3);
#pragma unroll
    for (int mt = 0; mt < 5; mt++) {
#pragma unroll
        for (int nt = 0; nt < 2; nt++) {
            int co = c0w + mt * 16 + rl;
            int b  = b0w + nt * 8 + cl;
            op[(size_t)b * CCO + co]           = acc[mt][nt][0];
            op[(size_t)(b + 1) * CCO + co]     = acc[mt][nt][1];
            op[(size_t)b * CCO + co + 8]       = acc[mt][nt][2];
            op[(size_t)(b + 1) * CCO + co + 8] = acc[mt][nt][3];
        }
    }
}

// ---------------------------------------------------------------------------
// Kernel 2: 4-way split reduction over NSPLIT partials + squash.
// grid = 128 (b), block = 640 (4 groups x 160 co).
// ---------------------------------------------------------------------------
__global__ void __launch_bounds__(640, 2)
digitcaps_squash_kernel(float* __restrict__ out)
{
    __shared__ float red[4][CCO];
    const int b  = blockIdx.x;
    const int t  = threadIdx.x;
    const int g  = t / CCO;          // 0..3
    const int co = t - g * CCO;      // 0..159
    const float* p = g_partial + (size_t)b * CCO + co;

    float s = 0.f;
#pragma unroll
    for (int k = 0; k < NSPLIT / 4; k++)
        s += __ldg(p + (size_t)(g * (NSPLIT / 4) + k) * (RB * CCO));
    red[g][co] = s;
    __syncthreads();

    if (g == 0) {
        float tot = red[0][co] + red[1][co] + red[2][co] + red[3][co];
        float sm = tot * (1.0f / (float)RROUTE);
        float sq = sm * sm;
#pragma unroll
        for (int m = 8; m >= 1; m >>= 1)
            sq += __shfl_xor_sync(0xffffffffu, sq, m, 16);
        out[(size_t)b * CCO + co] = sm * sqrtf(sq) / (1.0f + sq);
    }
}

// ---------------------------------------------------------------------------
extern "C" void kernel_launch(void* const* d_in, const int* in_sizes, int n_in,
                              void* d_out, int out_size)
{
    const float* x = (const float*)d_in[0];   // [128, 4608, 8]
    const float* W = (const float*)d_in[1];   // [1, 4608, 10, 16, 8]
    float* out = (float*)d_out;               // [128, 10, 16]

    digitcaps_mma_kernel<<<NSPLIT, NTHREADS>>>(x, W);
    digitcaps_squash_kernel<<<RB, 640>>>(out);
}

// round 7
// speedup vs baseline: 7.0265x; 1.4537x over previous
#include <cuda_runtime.h>
#include <cstdint>

// Problem constants
#define RB      128         // batch  (GEMM N)
#define RROUTE  4608        // routes
#define CCO     160         // C*O    (GEMM M)
#define II      8

// K-split
#define NSPLIT  144         // CTAs
#define CHUNK_R 32          // routes per CTA (K=256)
#define CK_R    4           // routes per k-chunk
#define KCH     32          // k per chunk
#define NCH     8
#define NTHREADS 512

// smem rows (bytes), padded & 16B aligned, ldmatrix conflict-free
#define A_ROW   80          // W tile row: 40 fp16 (32 used)
#define B_ROW   272         // x tile row: 136 fp16 (128 used)
#define OFF_A   0
#define OFF_B   (CCO * A_ROW)            // 12800
#define BUFB    (OFF_B + KCH * B_ROW)    // 21504 per buffer
#define SMEM_SZ (2 * BUFB)               // 43008 static (double buffered, <48KB)

// partial results [NSPLIT][B][CO]
__device__ float g_partial[NSPLIT * RB * CCO];

// ---------------- helpers ----------------
__device__ __forceinline__ uint32_t smem_u32(const void* p) {
    uint32_t a;
    asm("{ .reg .u64 t; cvta.to.shared.u64 t, %1; cvt.u32.u64 %0, t; }" : "=r"(a) : "l"(p));
    return a;
}
// pack two f32 -> f16x2 (e0 low half, e1 high half)
__device__ __forceinline__ uint32_t packh(float e0, float e1) {
    uint32_t d;
    asm("cvt.rn.f16x2.f32 %0, %1, %2;" : "=r"(d) : "f"(e1), "f"(e0));
    return d;
}
__device__ __forceinline__ void sts32(uint32_t a, uint32_t r) {
    asm volatile("st.shared.b32 [%0], %1;" :: "r"(a), "r"(r) : "memory");
}
__device__ __forceinline__ void sts64(uint32_t a, uint32_t r0, uint32_t r1) {
    asm volatile("st.shared.v2.b32 [%0], {%1, %2};" :: "r"(a), "r"(r0), "r"(r1) : "memory");
}
__device__ __forceinline__ void ldmx4(uint32_t* r, uint32_t a) {
    asm volatile("ldmatrix.sync.aligned.m8n8.x4.shared.b16 {%0,%1,%2,%3}, [%4];"
                 : "=r"(r[0]), "=r"(r[1]), "=r"(r[2]), "=r"(r[3]) : "r"(a));
}
__device__ __forceinline__ void ldmx2t(uint32_t* r, uint32_t a) {
    asm volatile("ldmatrix.sync.aligned.m8n8.x2.trans.shared.b16 {%0,%1}, [%2];"
                 : "=r"(r[0]), "=r"(r[1]) : "r"(a));
}
__device__ __forceinline__ void mma16816(float* d, const uint32_t* a, const uint32_t* b) {
    asm volatile(
        "mma.sync.aligned.m16n8k16.row.col.f32.f16.f16.f32 "
        "{%0,%1,%2,%3}, {%4,%5,%6,%7}, {%8,%9}, {%0,%1,%2,%3};"
        : "+f"(d[0]), "+f"(d[1]), "+f"(d[2]), "+f"(d[3])
        : "r"(a[0]), "r"(a[1]), "r"(a[2]), "r"(a[3]), "r"(b[0]), "r"(b[1]));
}
__device__ __forceinline__ float f4elem(const float4& v, int j) {
    switch (j) { case 0: return v.x; case 1: return v.y; case 2: return v.z; default: return v.w; }
}

// ---------------------------------------------------------------------------
// Kernel 1: fp16 mma.sync partial GEMM (single product; fp32 accumulate).
// D[co][b] (per CTA) = sum_{k in 256-slab} W_k[co] * x_k[b]
// 16 warps: 2 (M=co, 80 each) x 8 (N=b, 16 each). Warp tile 80x16 = 5x2 mma tiles.
// Double-buffered 2x21.5KB static smem; one barrier per chunk.
// ---------------------------------------------------------------------------
__global__ void __launch_bounds__(NTHREADS, 1)
digitcaps_mma_kernel(const float* __restrict__ x, const float* __restrict__ W)
{
    __shared__ __align__(16) char smem_raw[SMEM_SZ];
    const uint32_t tiles = smem_u32(smem_raw);

    const int tid = threadIdx.x;
    const int lid = tid & 31;
    const int wid = tid >> 5;
    const int wm  = wid & 1;          // M-warp (co)
    const int wn  = wid >> 1;         // N-warp (b)
    const int c0w = wm * 80;
    const int b0w = wn * 16;
    const int r0  = blockIdx.x * CHUNK_R;

    // x conversion task: b-pair bp, quarter q (k = q*4 + j)
    const int bp = tid >> 3;
    const int q  = tid & 7;

    float acc[5][2][4];
#pragma unroll
    for (int mt = 0; mt < 5; mt++)
#pragma unroll
        for (int nt = 0; nt < 2; nt++)
#pragma unroll
            for (int e = 0; e < 4; e++) acc[mt][nt][e] = 0.f;

    float4 px0, px1, pw[3];

    auto ldg_chunk = [&](int ck) {
        const int rc0 = r0 + ck * CK_R;
        const float4* xb = (const float4*)(x + ((size_t)(2 * bp) * RROUTE + rc0) * II);
        px0 = __ldg(xb + q);
        px1 = __ldg(xb + (RROUTE * II / 4) + q);     // row b+1
#pragma unroll
        for (int t = 0; t < 3; t++) {
            int idx = tid + t * NTHREADS;
            if (idx < 1280) {
                int rr = idx / 320, rem = idx - rr * 320;
                int co = rem >> 1, ih = rem & 1;
                pw[t] = __ldg((const float4*)(W + ((size_t)(rc0 + rr) * CCO + co) * II) + ih);
            }
        }
    };

    auto sts_chunk = [&](uint32_t bb) {
        // x -> B tile [k][b] (transpose during store; fp16 pair (b, b+1) per word)
#pragma unroll
        for (int j = 0; j < 4; j++) {
            uint32_t h = packh(f4elem(px0, j), f4elem(px1, j));
            sts32(tiles + bb + OFF_B + (uint32_t)((q * 4 + j) * B_ROW + 4 * bp), h);
        }
        // W -> A tile [co][k] (natural, k-contiguous)
#pragma unroll
        for (int t = 0; t < 3; t++) {
            int idx = tid + t * NTHREADS;
            if (idx < 1280) {
                int rr = idx / 320, rem = idx - rr * 320;
                int co = rem >> 1, ih = rem & 1;
                uint32_t h0 = packh(pw[t].x, pw[t].y), h1 = packh(pw[t].z, pw[t].w);
                sts64(tiles + bb + OFF_A + (uint32_t)(co * A_ROW + rr * 16 + ih * 8), h0, h1);
            }
        }
    };

    auto compute = [&](uint32_t bb) {
#pragma unroll
        for (int ks = 0; ks < 2; ks++) {
            const uint32_t k0 = ks * 16;
            uint32_t bh[2][2];
            const uint32_t brow = k0 + (lid & 7) + ((lid >> 3) & 1) * 8;
#pragma unroll
            for (int nt = 0; nt < 2; nt++)
                ldmx2t(bh[nt], tiles + bb + OFF_B + brow * B_ROW + (uint32_t)(b0w + nt * 8) * 2);
#pragma unroll
            for (int mt = 0; mt < 5; mt++) {
                uint32_t ah[4];
                ldmx4(ah, tiles + bb + OFF_A
                          + (uint32_t)(c0w + mt * 16 + (lid & 15)) * A_ROW
                          + (k0 + (lid >> 4) * 8) * 2);
#pragma unroll
                for (int nt = 0; nt < 2; nt++)
                    mma16816(acc[mt][nt], ah, bh[nt]);
            }
        }
    };

    // pipeline: prefetch LDG(c+1) in regs over compute(c); STS into idle buffer
    ldg_chunk(0);
    sts_chunk(0);
    __syncthreads();
#pragma unroll 1
    for (int c = 0; c < NCH; c++) {
        const uint32_t bb = (uint32_t)(c & 1) * BUFB;
        if (c + 1 < NCH) ldg_chunk(c + 1);
        compute(bb);
        if (c + 1 < NCH) {
            sts_chunk((uint32_t)((c + 1) & 1) * BUFB);   // other buffer: no wait needed
            __syncthreads();
        }
    }

    // epilogue: acc -> g_partial[bid][b][co]
    float* op = g_partial + (size_t)blockIdx.x * (RB * CCO);
    const int rl = lid >> 2;
    const int cl = 2 * (lid & 3);
#pragma unroll
    for (int mt = 0; mt < 5; mt++) {
#pragma unroll
        for (int nt = 0; nt < 2; nt++) {
            int co = c0w + mt * 16 + rl;
            int b  = b0w + nt * 8 + cl;
            op[(size_t)b * CCO + co]           = acc[mt][nt][0];
            op[(size_t)(b + 1) * CCO + co]     = acc[mt][nt][1];
            op[(size_t)b * CCO + co + 8]       = acc[mt][nt][2];
            op[(size_t)(b + 1) * CCO + co + 8] = acc[mt][nt][3];
        }
    }
}

// ---------------------------------------------------------------------------
// Kernel 2: reduce partials + squash, v3.
// grid = (128 b, 2 co-halves), block = 320 (20 co-quads x 16 split-groups).
// float4 loads, smem tree reduce, capsule sums via smem (16-o groups aligned).
// ---------------------------------------------------------------------------
__global__ void __launch_bounds__(320, 4)
digitcaps_squash_kernel(float* __restrict__ out)
{
    __shared__ float4 red[16][20];
    __shared__ float  sv[80];

    const int b    = blockIdx.x;
    const int half = blockIdx.y;         // 0/1 -> co base 0/80 (capsule-aligned)
    const int t    = threadIdx.x;
    const int ql   = t % 20;             // co quad
    const int grp  = t / 20;             // split group 0..15 (9 splits each)

    const float4* p =
        (const float4*)(g_partial + (size_t)b * CCO + half * 80) + ql;

    float4 a = make_float4(0.f, 0.f, 0.f, 0.f);
#pragma unroll
    for (int j = 0; j < 9; j++) {
        float4 v = __ldg(p + (size_t)(grp * 9 + j) * (RB * CCO / 4));
        a.x += v.x; a.y += v.y; a.z += v.z; a.w += v.w;
    }
    red[grp][ql] = a;
    __syncthreads();

    if (t < 80) {
        const int qq = t >> 2, e = t & 3;
        float s = 0.f;
#pragma unroll
        for (int g = 0; g < 16; g++)
            s += ((const float*)&red[g][qq])[e];
        s *= (1.0f / (float)RROUTE);
        sv[t] = s;
    }
    __syncthreads();

    if (t < 80) {
        const int base = (t >> 4) << 4;     // capsule start within the 80
        float sq = 0.f;
#pragma unroll
        for (int o = 0; o < 16; o++) {
            float v = sv[base + o];
            sq += v * v;
        }
        float s = sv[t];
        out[(size_t)b * CCO + half * 80 + t] = s * sqrtf(sq) / (1.0f + sq);
    }
}

// ---------------------------------------------------------------------------
extern "C" void kernel_launch(void* const* d_in, const int* in_sizes, int n_in,
                              void* d_out, int out_size)
{
    const float* x = (const float*)d_in[0];   // [128, 4608, 8]
    const float* W = (const float*)d_in[1];   // [1, 4608, 10, 16, 8]
    float* out = (float*)d_out;               // [128, 10, 16]

    digitcaps_mma_kernel<<<NSPLIT, NTHREADS>>>(x, W);
    digitcaps_squash_kernel<<<dim3(RB, 2), 320>>>(out);
}